// round 6
// baseline (speedup 1.0000x reference)
#include <cuda_runtime.h>
#include <cuda_bf16.h>
#include <cstdint>

#define B_  4
#define C_  128
#define N_  4096
#define CO_ 128
#define NKT 128

// -------- scratch device globals --------
__device__ uint32_t g_Qh[B_ * 4096 * 64];     // [b][i][crow] bf16x2 hi
__device__ uint32_t g_Ql[B_ * 4096 * 64];     // lo
__device__ uint32_t g_Kf[B_ * NKT * 4096];    // [b][kt][ ((kc*4+jf)*32+lane)*4 + slot ]
__device__ uint32_t g_Vf[B_ * NKT * 4096];    // [b][kt][ ((kc*16+nf)*32+lane)*2 + half ]
__device__ float    g_SA[B_ * C_ * N_];

// -------- helpers --------
__device__ __forceinline__ uint32_t f2tf32(float x) {
    uint32_t r;
    asm("cvt.rna.tf32.f32 %0, %1;" : "=r"(r) : "f"(x));
    return r;
}
__device__ __forceinline__ void bf16_split(float x, uint16_t& h, uint16_t& l) {
    __nv_bfloat16 hb = __float2bfloat16_rn(x);
    float hf = __bfloat162float(hb);
    __nv_bfloat16 lb = __float2bfloat16_rn(x - hf);
    h = __bfloat16_as_ushort(hb);
    l = __bfloat16_as_ushort(lb);
}
__device__ __forceinline__ uint32_t pack16(uint16_t lo, uint16_t hi) {
    return (uint32_t)lo | ((uint32_t)hi << 16);
}
__device__ __forceinline__ void mma_tf32(float* c, const uint32_t* a,
                                         uint32_t b0, uint32_t b1) {
    asm volatile(
        "mma.sync.aligned.m16n8k8.row.col.f32.tf32.tf32.f32 "
        "{%0,%1,%2,%3}, {%4,%5,%6,%7}, {%8,%9}, {%0,%1,%2,%3};"
        : "+f"(c[0]), "+f"(c[1]), "+f"(c[2]), "+f"(c[3])
        : "r"(a[0]), "r"(a[1]), "r"(a[2]), "r"(a[3]), "r"(b0), "r"(b1));
}
__device__ __forceinline__ void mma_bf16(float* c, const uint32_t* a,
                                         uint32_t b0, uint32_t b1) {
    asm volatile(
        "mma.sync.aligned.m16n8k16.row.col.f32.bf16.bf16.f32 "
        "{%0,%1,%2,%3}, {%4,%5,%6,%7}, {%8,%9}, {%0,%1,%2,%3};"
        : "+f"(c[0]), "+f"(c[1]), "+f"(c[2]), "+f"(c[3])
        : "r"(a[0]), "r"(a[1]), "r"(a[2]), "r"(a[3]), "r"(b0), "r"(b1));
}
__device__ __forceinline__ void cp_async16(uint32_t dst, const void* src) {
    asm volatile("cp.async.cg.shared.global [%0], [%1], 16;" :: "r"(dst), "l"(src));
}
__device__ __forceinline__ void cp_commit() { asm volatile("cp.async.commit_group;"); }
__device__ __forceinline__ void cp_wait1()  { asm volatile("cp.async.wait_group 1;"); }

// ---------------------------------------------------------------------------
// Shared GEMM body for projections (round-1 structure: 256 thr, 4o x 8n tile)
// Computes acc[4][8] for channels o0..o0+3, positions nblk*64+n0..+7, then
// the caller-specific epilogue writes it out. EPI: 0=Q, 1=K, 2=V.
// ---------------------------------------------------------------------------
template <int EPI>
__global__ __launch_bounds__(256) void proj_pack_kernel(
    const float* __restrict__ src, const float* __restrict__ W,
    const float* __restrict__ bias)
{
    __shared__ float Wt[32][132];
    __shared__ float xs[32][64];

    const int t = threadIdx.x, nblk = blockIdx.x, b = blockIdx.y;
    const int n0 = 8 * (t & 7), o0 = 4 * (t >> 3);

    float acc[4][8];
#pragma unroll
    for (int i = 0; i < 4; i++)
#pragma unroll
        for (int j = 0; j < 8; j++) acc[i][j] = 0.f;

    const float* srcB = src + (size_t)b * C_ * N_ + (size_t)nblk * 64;

    for (int k0 = 0; k0 < C_; k0 += 32) {
        for (int v = t; v < 1024; v += 256) {
            int o = v >> 3, q = v & 7;
            float4 w = *(const float4*)(W + (size_t)o * C_ + k0 + 4 * q);
            Wt[4 * q + 0][o] = w.x;
            Wt[4 * q + 1][o] = w.y;
            Wt[4 * q + 2][o] = w.z;
            Wt[4 * q + 3][o] = w.w;
        }
        for (int v = t; v < 512; v += 256) {
            int k = v >> 4, q = (v & 15) * 4;
            *(float4*)&xs[k][q] = *(const float4*)(srcB + (size_t)(k0 + k) * N_ + q);
        }
        __syncthreads();

#pragma unroll
        for (int k = 0; k < 32; k++) {
            float4 w  = *(float4*)&Wt[k][o0];
            float4 xa = *(float4*)&xs[k][n0];
            float4 xb = *(float4*)&xs[k][n0 + 4];
            float wv[4] = {w.x, w.y, w.z, w.w};
            float xv[8] = {xa.x, xa.y, xa.z, xa.w, xb.x, xb.y, xb.z, xb.w};
#pragma unroll
            for (int i = 0; i < 4; i++)
#pragma unroll
                for (int j = 0; j < 8; j++)
                    acc[i][j] = fmaf(wv[i], xv[j], acc[i][j]);
        }
        __syncthreads();
    }

    const float b0v = bias[o0], b1v = bias[o0 + 1], b2v = bias[o0 + 2], b3v = bias[o0 + 3];

    if (EPI == 0) {
        // Q: [b][i][crow] hi/lo packed pairs of channels
        const int crow = o0 >> 1;
#pragma unroll
        for (int jj = 0; jj < 8; jj++) {
            int n = nblk * 64 + n0 + jj;
            uint16_t h0, l0, h1, l1, h2, l2, h3, l3;
            bf16_split(acc[0][jj] + b0v, h0, l0);
            bf16_split(acc[1][jj] + b1v, h1, l1);
            bf16_split(acc[2][jj] + b2v, h2, l2);
            bf16_split(acc[3][jj] + b3v, h3, l3);
            size_t qb = ((size_t)b * 4096 + n) * 64 + crow;
            g_Qh[qb]     = pack16(h0, h1);
            g_Qh[qb + 1] = pack16(h2, h3);
            g_Ql[qb]     = pack16(l0, l1);
            g_Ql[qb + 1] = pack16(l2, l3);
        }
    } else if (EPI == 1) {
        // K: frag-packed uint4 {bh0,bh1,bl0,bl1}, element slots written singly
#pragma unroll
        for (int jj = 0; jj < 8; jj++) {
            int n = nblk * 64 + n0 + jj;
            int kt = n >> 5, j = n & 31;
            int jf = j >> 3, g2 = j & 7;
            uint16_t h0, l0, h1, l1, h2, l2, h3, l3;
            bf16_split(acc[0][jj] + b0v, h0, l0);
            bf16_split(acc[1][jj] + b1v, h1, l1);
            bf16_split(acc[2][jj] + b2v, h2, l2);
            bf16_split(acc[3][jj] + b3v, h3, l3);
            uint32_t hip[2] = {pack16(h0, h1), pack16(h2, h3)};
            uint32_t lop[2] = {pack16(l0, l1), pack16(l2, l3)};
            size_t base = ((size_t)b * NKT + kt) * 4096;
#pragma unroll
            for (int p = 0; p < 2; p++) {
                int cr  = (o0 >> 1) + p;
                int kc  = cr >> 3, r8 = cr & 7;
                int tidw = r8 & 3, half = r8 >> 2;
                int lane = g2 * 4 + tidw;
                size_t e = base + (size_t)(((kc * 4 + jf) * 32 + lane)) * 4;
                g_Kf[e + half]     = hip[p];
                g_Kf[e + 2 + half] = lop[p];
            }
        }
    } else {
        // V: frag-packed tf32 uint2 {b0,b1}
#pragma unroll
        for (int i = 0; i < 4; i++) {
            int c = o0 + i;
            int nf = c >> 3, g2 = c & 7;
            float bv = bias[c];
#pragma unroll
            for (int jj = 0; jj < 8; jj++) {
                int n = nblk * 64 + n0 + jj;
                int kt = n >> 5, j = n & 31;
                int kc = j >> 3, jm = j & 7;
                int tidj = jm & 3, half = jm >> 2;
                int lane = g2 * 4 + tidj;
                size_t e = ((size_t)b * NKT + kt) * 4096 +
                           (size_t)((kc * 16 + nf) * 32 + lane) * 2 + half;
                g_Vf[e] = f2tf32(acc[i][jj] + bv);
            }
        }
    }
}

// ---------------------------------------------------------------------------
// out-proj (fp32, round-1 style)
// ---------------------------------------------------------------------------
__global__ __launch_bounds__(256) void proj_kernel(
    const float* __restrict__ src, const float* __restrict__ W,
    const float* __restrict__ bias, float* __restrict__ dst)
{
    __shared__ float Wt[32][132];
    __shared__ float xs[32][64];

    const int t = threadIdx.x, nblk = blockIdx.x, b = blockIdx.y;
    const int n0 = 8 * (t & 7), o0 = 4 * (t >> 3);

    float acc[4][8];
#pragma unroll
    for (int i = 0; i < 4; i++)
#pragma unroll
        for (int j = 0; j < 8; j++) acc[i][j] = 0.f;

    const float* srcB = src + (size_t)b * C_ * N_ + (size_t)nblk * 64;

    for (int k0 = 0; k0 < C_; k0 += 32) {
        for (int v = t; v < 1024; v += 256) {
            int o = v >> 3, q = v & 7;
            float4 w = *(const float4*)(W + (size_t)o * C_ + k0 + 4 * q);
            Wt[4 * q + 0][o] = w.x;
            Wt[4 * q + 1][o] = w.y;
            Wt[4 * q + 2][o] = w.z;
            Wt[4 * q + 3][o] = w.w;
        }
        for (int v = t; v < 512; v += 256) {
            int k = v >> 4, q = (v & 15) * 4;
            *(float4*)&xs[k][q] = *(const float4*)(srcB + (size_t)(k0 + k) * N_ + q);
        }
        __syncthreads();

#pragma unroll
        for (int k = 0; k < 32; k++) {
            float4 w  = *(float4*)&Wt[k][o0];
            float4 xa = *(float4*)&xs[k][n0];
            float4 xb = *(float4*)&xs[k][n0 + 4];
            float wv[4] = {w.x, w.y, w.z, w.w};
            float xv[8] = {xa.x, xa.y, xa.z, xa.w, xb.x, xb.y, xb.z, xb.w};
#pragma unroll
            for (int i = 0; i < 4; i++)
#pragma unroll
                for (int j = 0; j < 8; j++)
                    acc[i][j] = fmaf(wv[i], xv[j], acc[i][j]);
        }
        __syncthreads();
    }

#pragma unroll
    for (int i = 0; i < 4; i++) {
        float bv = bias[o0 + i];
        float* drow = dst + ((size_t)b * 128 + (o0 + i)) * N_ + (size_t)nblk * 64 + n0;
        *(float4*)(drow)     = make_float4(acc[i][0] + bv, acc[i][1] + bv, acc[i][2] + bv, acc[i][3] + bv);
        *(float4*)(drow + 4) = make_float4(acc[i][4] + bv, acc[i][5] + bv, acc[i][6] + bv, acc[i][7] + bv);
    }
}

// ---------------------------------------------------------------------------
// attn: bf16-split QK^T + tf32 PV, frag-packed smem, cp.async double buffer.
// Block = 128 threads (4 warps), 64-query tile, 32-key tiles.
// ---------------------------------------------------------------------------
// smem (uints)
#define OFF_K 0                     // [2][4096]
#define OFF_V 8192                  // [2][4096]
#define OFF_P 16384                 // [64][36]
#define SM_UINTS 18688
#define ATTN_SMEM_BYTES (SM_UINTS * 4)

__global__ __launch_bounds__(128) void attn_kernel(
    const float* __restrict__ x, const float* __restrict__ gamma)
{
    extern __shared__ uint32_t smu[];
    uint32_t* Ps = smu + OFF_P;

    const int t = threadIdx.x;
    const int w = t >> 5, lane = t & 31;
    const int g2 = lane >> 2, tid = lane & 3;
    const int qblk = blockIdx.x, b = blockIdx.y;
    const int N0 = qblk * 64;
    const int I0 = N0 + 16 * w;

    const uint32_t sbase = (uint32_t)__cvta_generic_to_shared(smu);

    // ---- Q A-fragments into registers ----
    uint32_t qh[8][4], ql[8][4];
    {
        const uint32_t* Qhg = g_Qh + ((size_t)b * 4096 + I0) * 64;
        const uint32_t* Qlg = g_Ql + ((size_t)b * 4096 + I0) * 64;
        const int r0c = g2 * 64, r8c = (g2 + 8) * 64;
#pragma unroll
        for (int kc = 0; kc < 8; kc++) {
            int cl = 8 * kc + tid;
            qh[kc][0] = Qhg[r0c + cl];     qh[kc][1] = Qhg[r8c + cl];
            qh[kc][2] = Qhg[r0c + cl + 4]; qh[kc][3] = Qhg[r8c + cl + 4];
            ql[kc][0] = Qlg[r0c + cl];     ql[kc][1] = Qlg[r8c + cl];
            ql[kc][2] = Qlg[r0c + cl + 4]; ql[kc][3] = Qlg[r8c + cl + 4];
        }
    }

    const uint32_t* Kg = g_Kf + (size_t)b * NKT * 4096;
    const uint32_t* Vg = g_Vf + (size_t)b * NKT * 4096;

    auto issue = [&](int s, int kt) {
#pragma unroll
        for (int r = 0; r < 8; r++) {
            int i4 = t + 128 * r;   // uint4 index 0..1023
            cp_async16(sbase + (OFF_K + s * 4096) * 4 + i4 * 16,
                       Kg + (size_t)kt * 4096 + i4 * 4);
            cp_async16(sbase + (OFF_V + s * 4096) * 4 + i4 * 16,
                       Vg + (size_t)kt * 4096 + i4 * 4);
        }
    };

    issue(0, 0); cp_commit();
    issue(1, 1); cp_commit();

    float oacc[16][4];
#pragma unroll
    for (int nf = 0; nf < 16; nf++)
#pragma unroll
        for (int r = 0; r < 4; r++) oacc[nf][r] = 0.f;
    float m0 = -1e30f, m1 = -1e30f, l0 = 0.f, l1 = 0.f;

    const int r0 = 16 * w + g2;

    for (int kt = 0; kt < NKT; kt++) {
        cp_wait1();
        __syncthreads();
        const int s = kt & 1;
        const uint32_t* Kf = smu + OFF_K + s * 4096;
        const uint32_t* Vf = smu + OFF_V + s * 4096;

        // ---- S = Q^T K (bf16 split, LDS.128 frags) ----
        float sacc[4][4];
#pragma unroll
        for (int jf = 0; jf < 4; jf++)
#pragma unroll
            for (int r = 0; r < 4; r++) sacc[jf][r] = 0.f;

#pragma unroll
        for (int kc = 0; kc < 8; kc++) {
#pragma unroll
            for (int jf = 0; jf < 4; jf++) {
                uint4 kb = *(const uint4*)&Kf[(((kc * 4 + jf) * 32) + lane) * 4];
                mma_bf16(sacc[jf], qh[kc], kb.x, kb.y);
                mma_bf16(sacc[jf], ql[kc], kb.x, kb.y);
                mma_bf16(sacc[jf], qh[kc], kb.z, kb.w);
            }
        }

        // ---- online softmax ----
        float mx0 = fmaxf(fmaxf(sacc[0][0], sacc[0][1]), fmaxf(sacc[1][0], sacc[1][1]));
        mx0 = fmaxf(mx0, fmaxf(fmaxf(sacc[2][0], sacc[2][1]), fmaxf(sacc[3][0], sacc[3][1])));
        float mx1 = fmaxf(fmaxf(sacc[0][2], sacc[0][3]), fmaxf(sacc[1][2], sacc[1][3]));
        mx1 = fmaxf(mx1, fmaxf(fmaxf(sacc[2][2], sacc[2][3]), fmaxf(sacc[3][2], sacc[3][3])));
        mx0 = fmaxf(mx0, __shfl_xor_sync(0xffffffffu, mx0, 1));
        mx0 = fmaxf(mx0, __shfl_xor_sync(0xffffffffu, mx0, 2));
        mx1 = fmaxf(mx1, __shfl_xor_sync(0xffffffffu, mx1, 1));
        mx1 = fmaxf(mx1, __shfl_xor_sync(0xffffffffu, mx1, 2));

        float mn0 = fmaxf(m0, mx0), mn1 = fmaxf(m1, mx1);
        float sc0 = __expf(m0 - mn0), sc1 = __expf(m1 - mn1);
        m0 = mn0; m1 = mn1;

        float rs0 = 0.f, rs1 = 0.f;
#pragma unroll
        for (int jf = 0; jf < 4; jf++) {
            float p00 = __expf(sacc[jf][0] - m0);
            float p01 = __expf(sacc[jf][1] - m0);
            float p10 = __expf(sacc[jf][2] - m1);
            float p11 = __expf(sacc[jf][3] - m1);
            rs0 += p00 + p01;
            rs1 += p10 + p11;
            int cbase = 8 * jf + 2 * tid;
            Ps[r0 * 36 + cbase]           = f2tf32(p00);
            Ps[r0 * 36 + cbase + 1]       = f2tf32(p01);
            Ps[(r0 + 8) * 36 + cbase]     = f2tf32(p10);
            Ps[(r0 + 8) * 36 + cbase + 1] = f2tf32(p11);
        }
        rs0 += __shfl_xor_sync(0xffffffffu, rs0, 1);
        rs0 += __shfl_xor_sync(0xffffffffu, rs0, 2);
        rs1 += __shfl_xor_sync(0xffffffffu, rs1, 1);
        rs1 += __shfl_xor_sync(0xffffffffu, rs1, 2);
        l0 = l0 * sc0 + rs0;
        l1 = l1 * sc1 + rs1;

#pragma unroll
        for (int nf = 0; nf < 16; nf++) {
            oacc[nf][0] *= sc0; oacc[nf][1] *= sc0;
            oacc[nf][2] *= sc1; oacc[nf][3] *= sc1;
        }
        __syncwarp();

        // ---- O += P V^T (tf32, LDS.64 frags) ----
#pragma unroll
        for (int kc = 0; kc < 4; kc++) {
            uint32_t pa[4];
            pa[0] = Ps[r0 * 36 + 8 * kc + tid];
            pa[1] = Ps[(r0 + 8) * 36 + 8 * kc + tid];
            pa[2] = Ps[r0 * 36 + 8 * kc + tid + 4];
            pa[3] = Ps[(r0 + 8) * 36 + 8 * kc + tid + 4];
#pragma unroll
            for (int nf = 0; nf < 16; nf++) {
                uint2 vb = *(const uint2*)&Vf[((kc * 16 + nf) * 32 + lane) * 2];
                mma_tf32(oacc[nf], pa, vb.x, vb.y);
            }
        }

        __syncthreads();
        if (kt + 2 < NKT) issue(s, kt + 2);
        cp_commit();
    }

    // ---- normalize, stage O, residual, write ----
    float* OSf = (float*)smu;       // [128][68] = 8704 floats, fits
    {
        float inv0 = 1.f / l0, inv1 = 1.f / l1;
#pragma unroll
        for (int nf = 0; nf < 16; nf++) {
            int c = 8 * nf + 2 * tid;
            OSf[c * 68 + r0]           = oacc[nf][0] * inv0;
            OSf[(c + 1) * 68 + r0]     = oacc[nf][1] * inv0;
            OSf[c * 68 + r0 + 8]       = oacc[nf][2] * inv1;
            OSf[(c + 1) * 68 + r0 + 8] = oacc[nf][3] * inv1;
        }
    }
    __syncthreads();

    const float gm = gamma[0];
    const float* xB  = x    + (size_t)b * C_ * N_ + N0;
    float*       saB = g_SA + (size_t)b * C_ * N_ + N0;
    for (int v = t; v < 2048; v += 128) {
        int c = v >> 4, q = (v & 15) * 4;
        float4 o  = *(float4*)&OSf[c * 68 + q];
        float4 xv = *(const float4*)(xB + (size_t)c * N_ + q);
        float4 rr = make_float4(gm * o.x + xv.x, gm * o.y + xv.y,
                                gm * o.z + xv.z, gm * o.w + xv.w);
        *(float4*)(saB + (size_t)c * N_ + q) = rr;
    }
}

// ---------------------------------------------------------------------------
extern "C" void kernel_launch(void* const* d_in, const int* in_sizes, int n_in,
                              void* d_out, int out_size)
{
    const float* x     = (const float*)d_in[0];
    const float* Wq    = (const float*)d_in[1];
    const float* bq    = (const float*)d_in[2];
    const float* Wk    = (const float*)d_in[3];
    const float* bk    = (const float*)d_in[4];
    const float* Wv    = (const float*)d_in[5];
    const float* bv    = (const float*)d_in[6];
    const float* gamma = (const float*)d_in[7];
    const float* Wo    = (const float*)d_in[8];
    const float* bo    = (const float*)d_in[9];
    float* out = (float*)d_out;

    float* SAp;
    cudaGetSymbolAddress((void**)&SAp, g_SA);

    cudaFuncSetAttribute(attn_kernel,
                         cudaFuncAttributeMaxDynamicSharedMemorySize, ATTN_SMEM_BYTES);

    dim3 grid(N_ / 64, B_);
    proj_pack_kernel<0><<<grid, 256>>>(x, Wq, bq);
    proj_pack_kernel<1><<<grid, 256>>>(x, Wk, bk);
    proj_pack_kernel<2><<<grid, 256>>>(x, Wv, bv);
    attn_kernel<<<grid, 128, ATTN_SMEM_BYTES>>>(x, gamma);
    proj_kernel<<<grid, 256>>>(SAp, Wo, bo, out);
}

// round 7
// speedup vs baseline: 1.0151x; 1.0151x over previous
#include <cuda_runtime.h>
#include <cuda_bf16.h>
#include <cstdint>

#define B_  4
#define C_  128
#define N_  4096
#define CO_ 128
#define NKT 128

// -------- scratch device globals --------
__device__ uint32_t g_Qh[B_ * 4096 * 64];     // [b][i][crow] bf16x2 hi
__device__ uint32_t g_Ql[B_ * 4096 * 64];     // lo
__device__ uint32_t g_Kf[B_ * NKT * 4096];    // frag-packed K tiles
__device__ uint32_t g_Vf[B_ * NKT * 4096];    // frag-packed V tiles
__device__ float    g_SA[B_ * C_ * N_];

// -------- helpers --------
__device__ __forceinline__ uint32_t f2tf32(float x) {
    uint32_t r;
    asm("cvt.rna.tf32.f32 %0, %1;" : "=r"(r) : "f"(x));
    return r;
}
__device__ __forceinline__ void bf16_split(float x, uint16_t& h, uint16_t& l) {
    __nv_bfloat16 hb = __float2bfloat16_rn(x);
    float hf = __bfloat162float(hb);
    __nv_bfloat16 lb = __float2bfloat16_rn(x - hf);
    h = __bfloat16_as_ushort(hb);
    l = __bfloat16_as_ushort(lb);
}
__device__ __forceinline__ uint32_t pack16(uint16_t lo, uint16_t hi) {
    return (uint32_t)lo | ((uint32_t)hi << 16);
}
__device__ __forceinline__ void mma_tf32(float* c, const uint32_t* a,
                                         uint32_t b0, uint32_t b1) {
    asm volatile(
        "mma.sync.aligned.m16n8k8.row.col.f32.tf32.tf32.f32 "
        "{%0,%1,%2,%3}, {%4,%5,%6,%7}, {%8,%9}, {%0,%1,%2,%3};"
        : "+f"(c[0]), "+f"(c[1]), "+f"(c[2]), "+f"(c[3])
        : "r"(a[0]), "r"(a[1]), "r"(a[2]), "r"(a[3]), "r"(b0), "r"(b1));
}
__device__ __forceinline__ void mma_bf16(float* c, const uint32_t* a,
                                         uint32_t b0, uint32_t b1) {
    asm volatile(
        "mma.sync.aligned.m16n8k16.row.col.f32.bf16.bf16.f32 "
        "{%0,%1,%2,%3}, {%4,%5,%6,%7}, {%8,%9}, {%0,%1,%2,%3};"
        : "+f"(c[0]), "+f"(c[1]), "+f"(c[2]), "+f"(c[3])
        : "r"(a[0]), "r"(a[1]), "r"(a[2]), "r"(a[3]), "r"(b0), "r"(b1));
}
__device__ __forceinline__ void cp_async16(uint32_t dst, const void* src) {
    asm volatile("cp.async.cg.shared.global [%0], [%1], 16;" :: "r"(dst), "l"(src));
}
__device__ __forceinline__ void cp_commit() { asm volatile("cp.async.commit_group;"); }
__device__ __forceinline__ void cp_wait1()  { asm volatile("cp.async.wait_group 1;"); }

// ---------------------------------------------------------------------------
// Projections with coalesced packing epilogues. EPI: 0=Q, 1=K, 2=V.
// Block: 256 threads, tile 128(o) x 64(n). Stage acc in smem [c][66], then
// regenerate frag-packed layouts with coalesced stores.
// ---------------------------------------------------------------------------
template <int EPI>
__global__ __launch_bounds__(256) void proj_pack_kernel(
    const float* __restrict__ src, const float* __restrict__ W,
    const float* __restrict__ bias)
{
    __shared__ float stage[128 * 66];          // 33792 B; aliases Wt/xs during GEMM
    float* Wt = stage;                         // [32][132]
    float* xs = stage + 32 * 132;              // [32][64]

    const int t = threadIdx.x, nblk = blockIdx.x, b = blockIdx.y;
    const int n0 = 8 * (t & 7), o0 = 4 * (t >> 3);

    float acc[4][8];
#pragma unroll
    for (int i = 0; i < 4; i++)
#pragma unroll
        for (int j = 0; j < 8; j++) acc[i][j] = 0.f;

    const float* srcB = src + (size_t)b * C_ * N_ + (size_t)nblk * 64;

    for (int k0 = 0; k0 < C_; k0 += 32) {
        for (int v = t; v < 1024; v += 256) {
            int o = v >> 3, q = v & 7;
            float4 w = *(const float4*)(W + (size_t)o * C_ + k0 + 4 * q);
            Wt[(4 * q + 0) * 132 + o] = w.x;
            Wt[(4 * q + 1) * 132 + o] = w.y;
            Wt[(4 * q + 2) * 132 + o] = w.z;
            Wt[(4 * q + 3) * 132 + o] = w.w;
        }
        for (int v = t; v < 512; v += 256) {
            int k = v >> 4, q = (v & 15) * 4;
            *(float4*)&xs[k * 64 + q] = *(const float4*)(srcB + (size_t)(k0 + k) * N_ + q);
        }
        __syncthreads();

#pragma unroll
        for (int k = 0; k < 32; k++) {
            float4 w  = *(float4*)&Wt[k * 132 + o0];
            float4 xa = *(float4*)&xs[k * 64 + n0];
            float4 xb = *(float4*)&xs[k * 64 + n0 + 4];
            float wv[4] = {w.x, w.y, w.z, w.w};
            float xv[8] = {xa.x, xa.y, xa.z, xa.w, xb.x, xb.y, xb.z, xb.w};
#pragma unroll
            for (int i = 0; i < 4; i++)
#pragma unroll
                for (int j = 0; j < 8; j++)
                    acc[i][j] = fmaf(wv[i], xv[j], acc[i][j]);
        }
        __syncthreads();
    }

    // ---- stage acc + bias into [c][66] ----
#pragma unroll
    for (int i = 0; i < 4; i++) {
        float bv = bias[o0 + i];
#pragma unroll
        for (int j = 0; j < 8; j++)
            stage[(o0 + i) * 66 + n0 + j] = acc[i][j] + bv;
    }
    __syncthreads();

    if (EPI == 0) {
        // Q: word [i][crow] = pack(bf16 of c=2crow, 2crow+1); hi and lo arrays
        for (int idx = t; idx < 4096; idx += 256) {
            int crow = idx & 63, nl = idx >> 6;
            int n = nblk * 64 + nl;
            float va = stage[(2 * crow) * 66 + nl];
            float vb = stage[(2 * crow + 1) * 66 + nl];
            uint16_t ha, la, hb, lb;
            bf16_split(va, ha, la);
            bf16_split(vb, hb, lb);
            size_t qb = ((size_t)b * 4096 + n) * 64 + crow;
            g_Qh[qb] = pack16(ha, hb);
            g_Ql[qb] = pack16(la, lb);
        }
    } else if (EPI == 1) {
        // K frag-packed: uint4 {hi(cr_a), hi(cr_b), lo(cr_a), lo(cr_b)}
#pragma unroll
        for (int it = 0; it < 2; it++) {
            size_t base = ((size_t)b * NKT + (size_t)nblk * 2 + it) * 4096;
            for (int u = t; u < 1024; u += 256) {
                int lane = u & 31;
                int jf   = (u >> 5) & 3;
                int kc   = u >> 7;
                int tidw = lane & 3, g2 = lane >> 2;
                int nl = it * 32 + 8 * jf + g2;
                int cr_a = 8 * kc + tidw;
                int cr_b = cr_a + 4;
                float x0 = stage[(2 * cr_a) * 66 + nl];
                float x1 = stage[(2 * cr_a + 1) * 66 + nl];
                float x2 = stage[(2 * cr_b) * 66 + nl];
                float x3 = stage[(2 * cr_b + 1) * 66 + nl];
                uint16_t h0, l0, h1, l1, h2, l2, h3, l3;
                bf16_split(x0, h0, l0);
                bf16_split(x1, h1, l1);
                bf16_split(x2, h2, l2);
                bf16_split(x3, h3, l3);
                uint4 w4 = make_uint4(pack16(h0, h1), pack16(h2, h3),
                                      pack16(l0, l1), pack16(l2, l3));
                *(uint4*)&g_Kf[base + (size_t)u * 4] = w4;
            }
        }
    } else {
        // V frag-packed: uint2 {tf32(j_half0), tf32(j_half1)}
#pragma unroll
        for (int it = 0; it < 2; it++) {
            size_t base = ((size_t)b * NKT + (size_t)nblk * 2 + it) * 4096;
            for (int u = t; u < 2048; u += 256) {
                int lane = u & 31;
                int nf   = (u >> 5) & 15;
                int kc   = u >> 9;
                int tidj = lane & 3, g2v = lane >> 2;
                int c  = 8 * nf + g2v;
                int j0 = 8 * kc + tidj;
                uint2 w2;
                w2.x = f2tf32(stage[c * 66 + it * 32 + j0]);
                w2.y = f2tf32(stage[c * 66 + it * 32 + j0 + 4]);
                *(uint2*)&g_Vf[base + (size_t)u * 2] = w2;
            }
        }
    }
}

// ---------------------------------------------------------------------------
// out-proj (fp32)
// ---------------------------------------------------------------------------
__global__ __launch_bounds__(256) void proj_kernel(
    const float* __restrict__ src, const float* __restrict__ W,
    const float* __restrict__ bias, float* __restrict__ dst)
{
    __shared__ float Wt[32][132];
    __shared__ float xs[32][64];

    const int t = threadIdx.x, nblk = blockIdx.x, b = blockIdx.y;
    const int n0 = 8 * (t & 7), o0 = 4 * (t >> 3);

    float acc[4][8];
#pragma unroll
    for (int i = 0; i < 4; i++)
#pragma unroll
        for (int j = 0; j < 8; j++) acc[i][j] = 0.f;

    const float* srcB = src + (size_t)b * C_ * N_ + (size_t)nblk * 64;

    for (int k0 = 0; k0 < C_; k0 += 32) {
        for (int v = t; v < 1024; v += 256) {
            int o = v >> 3, q = v & 7;
            float4 w = *(const float4*)(W + (size_t)o * C_ + k0 + 4 * q);
            Wt[4 * q + 0][o] = w.x;
            Wt[4 * q + 1][o] = w.y;
            Wt[4 * q + 2][o] = w.z;
            Wt[4 * q + 3][o] = w.w;
        }
        for (int v = t; v < 512; v += 256) {
            int k = v >> 4, q = (v & 15) * 4;
            *(float4*)&xs[k][q] = *(const float4*)(srcB + (size_t)(k0 + k) * N_ + q);
        }
        __syncthreads();

#pragma unroll
        for (int k = 0; k < 32; k++) {
            float4 w  = *(float4*)&Wt[k][o0];
            float4 xa = *(float4*)&xs[k][n0];
            float4 xb = *(float4*)&xs[k][n0 + 4];
            float wv[4] = {w.x, w.y, w.z, w.w};
            float xv[8] = {xa.x, xa.y, xa.z, xa.w, xb.x, xb.y, xb.z, xb.w};
#pragma unroll
            for (int i = 0; i < 4; i++)
#pragma unroll
                for (int j = 0; j < 8; j++)
                    acc[i][j] = fmaf(wv[i], xv[j], acc[i][j]);
        }
        __syncthreads();
    }

#pragma unroll
    for (int i = 0; i < 4; i++) {
        float bv = bias[o0 + i];
        float* drow = dst + ((size_t)b * 128 + (o0 + i)) * N_ + (size_t)nblk * 64 + n0;
        *(float4*)(drow)     = make_float4(acc[i][0] + bv, acc[i][1] + bv, acc[i][2] + bv, acc[i][3] + bv);
        *(float4*)(drow + 4) = make_float4(acc[i][4] + bv, acc[i][5] + bv, acc[i][6] + bv, acc[i][7] + bv);
    }
}

// ---------------------------------------------------------------------------
// attn: 256 threads / 8 warps, 128-query tile, 32-key tiles.
// bf16-split QK^T + tf32 PV, frag-packed smem, cp.async double buffer.
// ---------------------------------------------------------------------------
// smem (uints)
#define OFF_K 0                     // [2][4096]
#define OFF_V 8192                  // [2][4096]
#define OFF_P 16384                 // [128][36]
#define SM_UINTS (16384 + 128 * 36)
#define ATTN_SMEM_BYTES (SM_UINTS * 4)   // 83968 B

__global__ __launch_bounds__(256) void attn_kernel(
    const float* __restrict__ x, const float* __restrict__ gamma)
{
    extern __shared__ uint32_t smu[];
    uint32_t* Ps = smu + OFF_P;

    const int t = threadIdx.x;
    const int w = t >> 5, lane = t & 31;
    const int g2 = lane >> 2, tid = lane & 3;
    const int qblk = blockIdx.x, b = blockIdx.y;
    const int N0 = qblk * 128;
    const int I0 = N0 + 16 * w;

    const uint32_t sbase = (uint32_t)__cvta_generic_to_shared(smu);

    // ---- Q A-fragments into registers ----
    uint32_t qh[8][4], ql[8][4];
    {
        const uint32_t* Qhg = g_Qh + ((size_t)b * 4096 + I0) * 64;
        const uint32_t* Qlg = g_Ql + ((size_t)b * 4096 + I0) * 64;
        const int r0c = g2 * 64, r8c = (g2 + 8) * 64;
#pragma unroll
        for (int kc = 0; kc < 8; kc++) {
            int cl = 8 * kc + tid;
            qh[kc][0] = Qhg[r0c + cl];     qh[kc][1] = Qhg[r8c + cl];
            qh[kc][2] = Qhg[r0c + cl + 4]; qh[kc][3] = Qhg[r8c + cl + 4];
            ql[kc][0] = Qlg[r0c + cl];     ql[kc][1] = Qlg[r8c + cl];
            ql[kc][2] = Qlg[r0c + cl + 4]; ql[kc][3] = Qlg[r8c + cl + 4];
        }
    }

    const uint32_t* Kg = g_Kf + (size_t)b * NKT * 4096;
    const uint32_t* Vg = g_Vf + (size_t)b * NKT * 4096;

    auto issue = [&](int s, int kt) {
#pragma unroll
        for (int r = 0; r < 4; r++) {
            int i4 = t + 256 * r;   // uint4 index 0..1023
            cp_async16(sbase + (OFF_K + s * 4096) * 4 + i4 * 16,
                       Kg + (size_t)kt * 4096 + i4 * 4);
            cp_async16(sbase + (OFF_V + s * 4096) * 4 + i4 * 16,
                       Vg + (size_t)kt * 4096 + i4 * 4);
        }
    };

    issue(0, 0); cp_commit();
    issue(1, 1); cp_commit();

    float oacc[16][4];
#pragma unroll
    for (int nf = 0; nf < 16; nf++)
#pragma unroll
        for (int r = 0; r < 4; r++) oacc[nf][r] = 0.f;
    float m0 = -1e30f, m1 = -1e30f, l0 = 0.f, l1 = 0.f;

    const int r0 = 16 * w + g2;

    for (int kt = 0; kt < NKT; kt++) {
        cp_wait1();
        __syncthreads();
        const int s = kt & 1;
        const uint32_t* Kf = smu + OFF_K + s * 4096;
        const uint32_t* Vf = smu + OFF_V + s * 4096;

        // ---- S = Q^T K (bf16 split, LDS.128 frags) ----
        float sacc[4][4];
#pragma unroll
        for (int jf = 0; jf < 4; jf++)
#pragma unroll
            for (int r = 0; r < 4; r++) sacc[jf][r] = 0.f;

#pragma unroll
        for (int kc = 0; kc < 8; kc++) {
#pragma unroll
            for (int jf = 0; jf < 4; jf++) {
                uint4 kb = *(const uint4*)&Kf[(((kc * 4 + jf) * 32) + lane) * 4];
                mma_bf16(sacc[jf], qh[kc], kb.x, kb.y);
                mma_bf16(sacc[jf], ql[kc], kb.x, kb.y);
                mma_bf16(sacc[jf], qh[kc], kb.z, kb.w);
            }
        }

        // ---- online softmax (per-warp, 16 rows) ----
        float mx0 = fmaxf(fmaxf(sacc[0][0], sacc[0][1]), fmaxf(sacc[1][0], sacc[1][1]));
        mx0 = fmaxf(mx0, fmaxf(fmaxf(sacc[2][0], sacc[2][1]), fmaxf(sacc[3][0], sacc[3][1])));
        float mx1 = fmaxf(fmaxf(sacc[0][2], sacc[0][3]), fmaxf(sacc[1][2], sacc[1][3]));
        mx1 = fmaxf(mx1, fmaxf(fmaxf(sacc[2][2], sacc[2][3]), fmaxf(sacc[3][2], sacc[3][3])));
        mx0 = fmaxf(mx0, __shfl_xor_sync(0xffffffffu, mx0, 1));
        mx0 = fmaxf(mx0, __shfl_xor_sync(0xffffffffu, mx0, 2));
        mx1 = fmaxf(mx1, __shfl_xor_sync(0xffffffffu, mx1, 1));
        mx1 = fmaxf(mx1, __shfl_xor_sync(0xffffffffu, mx1, 2));

        float mn0 = fmaxf(m0, mx0), mn1 = fmaxf(m1, mx1);
        float sc0 = __expf(m0 - mn0), sc1 = __expf(m1 - mn1);
        m0 = mn0; m1 = mn1;

        float rs0 = 0.f, rs1 = 0.f;
#pragma unroll
        for (int jf = 0; jf < 4; jf++) {
            float p00 = __expf(sacc[jf][0] - m0);
            float p01 = __expf(sacc[jf][1] - m0);
            float p10 = __expf(sacc[jf][2] - m1);
            float p11 = __expf(sacc[jf][3] - m1);
            rs0 += p00 + p01;
            rs1 += p10 + p11;
            int cbase = 8 * jf + 2 * tid;
            Ps[r0 * 36 + cbase]           = f2tf32(p00);
            Ps[r0 * 36 + cbase + 1]       = f2tf32(p01);
            Ps[(r0 + 8) * 36 + cbase]     = f2tf32(p10);
            Ps[(r0 + 8) * 36 + cbase + 1] = f2tf32(p11);
        }
        rs0 += __shfl_xor_sync(0xffffffffu, rs0, 1);
        rs0 += __shfl_xor_sync(0xffffffffu, rs0, 2);
        rs1 += __shfl_xor_sync(0xffffffffu, rs1, 1);
        rs1 += __shfl_xor_sync(0xffffffffu, rs1, 2);
        l0 = l0 * sc0 + rs0;
        l1 = l1 * sc1 + rs1;

#pragma unroll
        for (int nf = 0; nf < 16; nf++) {
            oacc[nf][0] *= sc0; oacc[nf][1] *= sc0;
            oacc[nf][2] *= sc1; oacc[nf][3] *= sc1;
        }
        __syncwarp();

        // ---- O += P V^T (tf32, LDS.64 frags) ----
#pragma unroll
        for (int kc = 0; kc < 4; kc++) {
            uint32_t pa[4];
            pa[0] = Ps[r0 * 36 + 8 * kc + tid];
            pa[1] = Ps[(r0 + 8) * 36 + 8 * kc + tid];
            pa[2] = Ps[r0 * 36 + 8 * kc + tid + 4];
            pa[3] = Ps[(r0 + 8) * 36 + 8 * kc + tid + 4];
#pragma unroll
            for (int nf = 0; nf < 16; nf++) {
                uint2 vb = *(const uint2*)&Vf[((kc * 16 + nf) * 32 + lane) * 2];
                mma_tf32(oacc[nf], pa, vb.x, vb.y);
            }
        }

        __syncthreads();
        if (kt + 2 < NKT) issue(s, kt + 2);
        cp_commit();
    }

    // ---- normalize, stage O [128c][132], residual, write ----
    float* OSf = (float*)smu;       // 128*132 = 16896 floats <= 20992 avail
    {
        float inv0 = 1.f / l0, inv1 = 1.f / l1;
#pragma unroll
        for (int nf = 0; nf < 16; nf++) {
            int c = 8 * nf + 2 * tid;
            OSf[c * 132 + r0]           = oacc[nf][0] * inv0;
            OSf[(c + 1) * 132 + r0]     = oacc[nf][1] * inv0;
            OSf[c * 132 + r0 + 8]       = oacc[nf][2] * inv1;
            OSf[(c + 1) * 132 + r0 + 8] = oacc[nf][3] * inv1;
        }
    }
    __syncthreads();

    const float gm = gamma[0];
    const float* xB  = x    + (size_t)b * C_ * N_ + N0;
    float*       saB = g_SA + (size_t)b * C_ * N_ + N0;
    for (int v = t; v < 4096; v += 256) {
        int c = v >> 5, q = (v & 31) * 4;
        float4 o  = *(float4*)&OSf[c * 132 + q];
        float4 xv = *(const float4*)(xB + (size_t)c * N_ + q);
        float4 rr = make_float4(gm * o.x + xv.x, gm * o.y + xv.y,
                                gm * o.z + xv.z, gm * o.w + xv.w);
        *(float4*)(saB + (size_t)c * N_ + q) = rr;
    }
}

// ---------------------------------------------------------------------------
extern "C" void kernel_launch(void* const* d_in, const int* in_sizes, int n_in,
                              void* d_out, int out_size)
{
    const float* x     = (const float*)d_in[0];
    const float* Wq    = (const float*)d_in[1];
    const float* bq    = (const float*)d_in[2];
    const float* Wk    = (const float*)d_in[3];
    const float* bk    = (const float*)d_in[4];
    const float* Wv    = (const float*)d_in[5];
    const float* bv    = (const float*)d_in[6];
    const float* gamma = (const float*)d_in[7];
    const float* Wo    = (const float*)d_in[8];
    const float* bo    = (const float*)d_in[9];
    float* out = (float*)d_out;

    float* SAp;
    cudaGetSymbolAddress((void**)&SAp, g_SA);

    cudaFuncSetAttribute(attn_kernel,
                         cudaFuncAttributeMaxDynamicSharedMemorySize, ATTN_SMEM_BYTES);

    dim3 pgrid(N_ / 64, B_);
    proj_pack_kernel<0><<<pgrid, 256>>>(x, Wq, bq);
    proj_pack_kernel<1><<<pgrid, 256>>>(x, Wk, bk);
    proj_pack_kernel<2><<<pgrid, 256>>>(x, Wv, bv);

    dim3 agrid(N_ / 128, B_);
    attn_kernel<<<agrid, 256, ATTN_SMEM_BYTES>>>(x, gamma);

    proj_kernel<<<pgrid, 256>>>(SAp, Wo, bo, out);
}

// round 9
// speedup vs baseline: 1.3539x; 1.3338x over previous
#include <cuda_runtime.h>
#include <cuda_fp16.h>
#include <cstdint>

#define B_  4
#define C_  128
#define N_  4096
#define CO_ 128
#define NKT 128            // 32-key tiles

// -------- scratch device globals --------
__device__ uint32_t g_Qh[B_ * 4096 * 64];     // [b][i][crow] fp16x2 hi (channel pairs)
__device__ uint32_t g_Ql[B_ * 4096 * 64];     // lo
__device__ uint32_t g_Kf[B_ * NKT * 2048];    // frag-packed fp16 K tiles (uint4 jf-pairs)
__device__ uint32_t g_Vf[B_ * NKT * 2048];    // frag-packed fp16 V tiles (uint4 nf-pairs)
__device__ float    g_SA[B_ * C_ * N_];

// -------- helpers --------
__device__ __forceinline__ uint32_t f16x2(float lo, float hi) {
    uint32_t r;
    asm("cvt.rn.f16x2.f32 %0, %1, %2;" : "=r"(r) : "f"(hi), "f"(lo));
    return r;
}
__device__ __forceinline__ void fp16_split(float x, float& h, float& l) {
    __half hh = __float2half_rn(x);
    h = __half2float(hh);
    l = x - h;
}
__device__ __forceinline__ void mma_fp16(float* c, const uint32_t* a,
                                         uint32_t b0, uint32_t b1) {
    asm volatile(
        "mma.sync.aligned.m16n8k16.row.col.f32.f16.f16.f32 "
        "{%0,%1,%2,%3}, {%4,%5,%6,%7}, {%8,%9}, {%0,%1,%2,%3};"
        : "+f"(c[0]), "+f"(c[1]), "+f"(c[2]), "+f"(c[3])
        : "r"(a[0]), "r"(a[1]), "r"(a[2]), "r"(a[3]), "r"(b0), "r"(b1));
}
__device__ __forceinline__ void cp_async16(uint32_t dst, const void* src) {
    asm volatile("cp.async.cg.shared.global [%0], [%1], 16;" :: "r"(dst), "l"(src));
}
__device__ __forceinline__ void cp_commit() { asm volatile("cp.async.commit_group;"); }
__device__ __forceinline__ void cp_wait1()  { asm volatile("cp.async.wait_group 1;"); }

// ---------------------------------------------------------------------------
// Projections. EPI: 0=Q, 1=K, 2=V. 256 threads, 128(o) x 64(n) tile.
// GEMM in fp32, epilogue packs fp16 fragment layouts with coalesced stores.
// ---------------------------------------------------------------------------
template <int EPI>
__global__ __launch_bounds__(256) void proj_pack_kernel(
    const float* __restrict__ src, const float* __restrict__ W,
    const float* __restrict__ bias)
{
    __shared__ float stage[128 * 66];          // aliases Wt/xs during GEMM
    float* Wt = stage;                         // [32][132]
    float* xs = stage + 32 * 132;              // [32][64]

    const int t = threadIdx.x, nblk = blockIdx.x, b = blockIdx.y;
    const int n0 = 8 * (t & 7), o0 = 4 * (t >> 3);

    float acc[4][8];
#pragma unroll
    for (int i = 0; i < 4; i++)
#pragma unroll
        for (int j = 0; j < 8; j++) acc[i][j] = 0.f;

    const float* srcB = src + (size_t)b * C_ * N_ + (size_t)nblk * 64;

    for (int k0 = 0; k0 < C_; k0 += 32) {
        for (int v = t; v < 1024; v += 256) {
            int o = v >> 3, q = v & 7;
            float4 w = *(const float4*)(W + (size_t)o * C_ + k0 + 4 * q);
            Wt[(4 * q + 0) * 132 + o] = w.x;
            Wt[(4 * q + 1) * 132 + o] = w.y;
            Wt[(4 * q + 2) * 132 + o] = w.z;
            Wt[(4 * q + 3) * 132 + o] = w.w;
        }
        for (int v = t; v < 512; v += 256) {
            int k = v >> 4, q = (v & 15) * 4;
            *(float4*)&xs[k * 64 + q] = *(const float4*)(srcB + (size_t)(k0 + k) * N_ + q);
        }
        __syncthreads();
#pragma unroll
        for (int k = 0; k < 32; k++) {
            float4 w  = *(float4*)&Wt[k * 132 + o0];
            float4 xa = *(float4*)&xs[k * 64 + n0];
            float4 xb = *(float4*)&xs[k * 64 + n0 + 4];
            float wv[4] = {w.x, w.y, w.z, w.w};
            float xv[8] = {xa.x, xa.y, xa.z, xa.w, xb.x, xb.y, xb.z, xb.w};
#pragma unroll
            for (int i = 0; i < 4; i++)
#pragma unroll
                for (int j = 0; j < 8; j++)
                    acc[i][j] = fmaf(wv[i], xv[j], acc[i][j]);
        }
        __syncthreads();
    }

#pragma unroll
    for (int i = 0; i < 4; i++) {
        float bv = bias[o0 + i];
#pragma unroll
        for (int j = 0; j < 8; j++)
            stage[(o0 + i) * 66 + n0 + j] = acc[i][j] + bv;
    }
    __syncthreads();

    if (EPI == 0) {
        // Q: word [i][crow] = fp16x2(c=2crow, 2crow+1), hi and lo arrays
        for (int idx = t; idx < 4096; idx += 256) {
            int crow = idx & 63, nl = idx >> 6;
            int n = nblk * 64 + nl;
            float ha, la, hb, lb;
            fp16_split(stage[(2 * crow) * 66 + nl], ha, la);
            fp16_split(stage[(2 * crow + 1) * 66 + nl], hb, lb);
            size_t qb = ((size_t)b * 4096 + n) * 64 + crow;
            g_Qh[qb] = f16x2(ha, hb);
            g_Ql[qb] = f16x2(la, lb);
        }
    } else if (EPI == 1) {
        // K: uint4 = {b0(jf even), b1(jf even), b0(jf odd), b1(jf odd)}
        // b0 = f16x2(K[c=16kc+2tid], K[c+1]) at key 8jf+g2 ; b1 = channels +8
#pragma unroll
        for (int it = 0; it < 2; it++) {
            size_t base = ((size_t)b * NKT + (size_t)nblk * 2 + it) * 2048;
            for (int u = t; u < 512; u += 256) {
                int lane = u & 31, jfp = (u >> 5) & 1, kc = u >> 6;
                int tid = lane & 3, g2 = lane >> 2;
                int nl_e = it * 32 + 8 * (2 * jfp) + g2;
                int nl_o = nl_e + 8;
                int c0 = 16 * kc + 2 * tid;
                uint4 w4;
                w4.x = f16x2(stage[c0 * 66 + nl_e],       stage[(c0 + 1) * 66 + nl_e]);
                w4.y = f16x2(stage[(c0 + 8) * 66 + nl_e], stage[(c0 + 9) * 66 + nl_e]);
                w4.z = f16x2(stage[c0 * 66 + nl_o],       stage[(c0 + 1) * 66 + nl_o]);
                w4.w = f16x2(stage[(c0 + 8) * 66 + nl_o], stage[(c0 + 9) * 66 + nl_o]);
                *(uint4*)&g_Kf[base + (size_t)u * 4] = w4;
            }
        }
    } else {
        // V: uint4 = {b0(nf even), b1(nf even), b0(nf odd), b1(nf odd)}
        // b0 = f16x2(V[j=16kc+2tid], V[j+1]) at channel 8nf+g2 ; b1 = keys +8
#pragma unroll
        for (int it = 0; it < 2; it++) {
            size_t base = ((size_t)b * NKT + (size_t)nblk * 2 + it) * 2048;
            for (int u = t; u < 512; u += 256) {
                int lane = u & 31, nfp = (u >> 5) & 7, kc = u >> 8;
                int tid = lane & 3, g2 = lane >> 2;
                int c_e = 8 * (2 * nfp) + g2;
                int c_o = c_e + 8;
                int j0 = it * 32 + 16 * kc + 2 * tid;
                uint4 w4;
                w4.x = f16x2(stage[c_e * 66 + j0],     stage[c_e * 66 + j0 + 1]);
                w4.y = f16x2(stage[c_e * 66 + j0 + 8], stage[c_e * 66 + j0 + 9]);
                w4.z = f16x2(stage[c_o * 66 + j0],     stage[c_o * 66 + j0 + 1]);
                w4.w = f16x2(stage[c_o * 66 + j0 + 8], stage[c_o * 66 + j0 + 9]);
                *(uint4*)&g_Vf[base + (size_t)u * 4] = w4;
            }
        }
    }
}

// ---------------------------------------------------------------------------
// out-proj (fp32)
// ---------------------------------------------------------------------------
__global__ __launch_bounds__(256) void proj_kernel(
    const float* __restrict__ src, const float* __restrict__ W,
    const float* __restrict__ bias, float* __restrict__ dst)
{
    __shared__ float Wt[32][132];
    __shared__ float xs[32][64];

    const int t = threadIdx.x, nblk = blockIdx.x, b = blockIdx.y;
    const int n0 = 8 * (t & 7), o0 = 4 * (t >> 3);

    float acc[4][8];
#pragma unroll
    for (int i = 0; i < 4; i++)
#pragma unroll
        for (int j = 0; j < 8; j++) acc[i][j] = 0.f;

    const float* srcB = src + (size_t)b * C_ * N_ + (size_t)nblk * 64;

    for (int k0 = 0; k0 < C_; k0 += 32) {
        for (int v = t; v < 1024; v += 256) {
            int o = v >> 3, q = v & 7;
            float4 w = *(const float4*)(W + (size_t)o * C_ + k0 + 4 * q);
            Wt[4 * q + 0][o] = w.x;
            Wt[4 * q + 1][o] = w.y;
            Wt[4 * q + 2][o] = w.z;
            Wt[4 * q + 3][o] = w.w;
        }
        for (int v = t; v < 512; v += 256) {
            int k = v >> 4, q = (v & 15) * 4;
            *(float4*)&xs[k][q] = *(const float4*)(srcB + (size_t)(k0 + k) * N_ + q);
        }
        __syncthreads();
#pragma unroll
        for (int k = 0; k < 32; k++) {
            float4 w  = *(float4*)&Wt[k][o0];
            float4 xa = *(float4*)&xs[k][n0];
            float4 xb = *(float4*)&xs[k][n0 + 4];
            float wv[4] = {w.x, w.y, w.z, w.w};
            float xv[8] = {xa.x, xa.y, xa.z, xa.w, xb.x, xb.y, xb.z, xb.w};
#pragma unroll
            for (int i = 0; i < 4; i++)
#pragma unroll
                for (int j = 0; j < 8; j++)
                    acc[i][j] = fmaf(wv[i], xv[j], acc[i][j]);
        }
        __syncthreads();
    }

#pragma unroll
    for (int i = 0; i < 4; i++) {
        float bv = bias[o0 + i];
        float* drow = dst + ((size_t)b * 128 + (o0 + i)) * N_ + (size_t)nblk * 64 + n0;
        *(float4*)(drow)     = make_float4(acc[i][0] + bv, acc[i][1] + bv, acc[i][2] + bv, acc[i][3] + bv);
        *(float4*)(drow + 4) = make_float4(acc[i][4] + bv, acc[i][5] + bv, acc[i][6] + bv, acc[i][7] + bv);
    }
}

// ---------------------------------------------------------------------------
// attn: fp16 mma flash attention, register-resident P.
// 256 threads / 8 warps, 128-query tile, 32-key tiles.
// ---------------------------------------------------------------------------
// smem (uints): K 2 stages x 2048, V 2 stages x 2048; epilogue reuses as O staging
#define OFF_K 0
#define OFF_V 4096
#define SM_UINTS (128 * 132)             // 16896 uints for O staging (covers 8192 pipeline)
#define ATTN_SMEM_BYTES (SM_UINTS * 4)

__global__ __launch_bounds__(256) void attn_kernel(
    const float* __restrict__ x, const float* __restrict__ gamma)
{
    extern __shared__ uint32_t smu[];

    const int t = threadIdx.x;
    const int w = t >> 5, lane = t & 31;
    const int g2 = lane >> 2, tid = lane & 3;
    const int qblk = blockIdx.x, b = blockIdx.y;
    const int N0 = qblk * 128;
    const int I0 = N0 + 16 * w;

    const uint32_t sbase = (uint32_t)__cvta_generic_to_shared(smu);

    // ---- Q A-fragments (fp16 hi/lo) into registers ----
    uint32_t qh[8][4], ql[8][4];
    {
        const uint32_t* Qhg = g_Qh + ((size_t)b * 4096 + I0) * 64;
        const uint32_t* Qlg = g_Ql + ((size_t)b * 4096 + I0) * 64;
        const int r0c = g2 * 64, r8c = (g2 + 8) * 64;
#pragma unroll
        for (int kc = 0; kc < 8; kc++) {
            int cl = 8 * kc + tid;
            qh[kc][0] = Qhg[r0c + cl];     qh[kc][1] = Qhg[r8c + cl];
            qh[kc][2] = Qhg[r0c + cl + 4]; qh[kc][3] = Qhg[r8c + cl + 4];
            ql[kc][0] = Qlg[r0c + cl];     ql[kc][1] = Qlg[r8c + cl];
            ql[kc][2] = Qlg[r0c + cl + 4]; ql[kc][3] = Qlg[r8c + cl + 4];
        }
    }

    const uint32_t* Kg = g_Kf + (size_t)b * NKT * 2048;
    const uint32_t* Vg = g_Vf + (size_t)b * NKT * 2048;

    auto issue = [&](int s, int kt) {
#pragma unroll
        for (int r = 0; r < 2; r++) {
            int i4 = t + 256 * r;       // uint4 index 0..511
            cp_async16(sbase + (OFF_K + s * 2048) * 4 + i4 * 16,
                       Kg + (size_t)kt * 2048 + i4 * 4);
            cp_async16(sbase + (OFF_V + s * 2048) * 4 + i4 * 16,
                       Vg + (size_t)kt * 2048 + i4 * 4);
        }
    };

    issue(0, 0); cp_commit();
    issue(1, 1); cp_commit();

    float oacc[16][4];
#pragma unroll
    for (int nf = 0; nf < 16; nf++)
#pragma unroll
        for (int r = 0; r < 4; r++) oacc[nf][r] = 0.f;
    float m0 = -1e30f, m1 = -1e30f, l0 = 0.f, l1 = 0.f;

    for (int kt = 0; kt < NKT; kt++) {
        cp_wait1();
        __syncthreads();
        const int s = kt & 1;
        const uint32_t* Kf = smu + OFF_K + s * 2048;
        const uint32_t* Vf = smu + OFF_V + s * 2048;

        // ---- S = Q^T K (2-term fp16 split, LDS.128 jf-pair frags) ----
        float sacc[4][4];
#pragma unroll
        for (int jf = 0; jf < 4; jf++)
#pragma unroll
            for (int r = 0; r < 4; r++) sacc[jf][r] = 0.f;

#pragma unroll
        for (int kc = 0; kc < 8; kc++) {
#pragma unroll
            for (int jfp = 0; jfp < 2; jfp++) {
                uint4 kb = *(const uint4*)&Kf[((kc * 2 + jfp) * 32 + lane) * 4];
                mma_fp16(sacc[2 * jfp],     qh[kc], kb.x, kb.y);
                mma_fp16(sacc[2 * jfp],     ql[kc], kb.x, kb.y);
                mma_fp16(sacc[2 * jfp + 1], qh[kc], kb.z, kb.w);
                mma_fp16(sacc[2 * jfp + 1], ql[kc], kb.z, kb.w);
            }
        }

        // ---- online softmax (rows r0 = 16w+g2, r0+8) ----
        float mx0 = fmaxf(fmaxf(sacc[0][0], sacc[0][1]), fmaxf(sacc[1][0], sacc[1][1]));
        mx0 = fmaxf(mx0, fmaxf(fmaxf(sacc[2][0], sacc[2][1]), fmaxf(sacc[3][0], sacc[3][1])));
        float mx1 = fmaxf(fmaxf(sacc[0][2], sacc[0][3]), fmaxf(sacc[1][2], sacc[1][3]));
        mx1 = fmaxf(mx1, fmaxf(fmaxf(sacc[2][2], sacc[2][3]), fmaxf(sacc[3][2], sacc[3][3])));
        mx0 = fmaxf(mx0, __shfl_xor_sync(0xffffffffu, mx0, 1));
        mx0 = fmaxf(mx0, __shfl_xor_sync(0xffffffffu, mx0, 2));
        mx1 = fmaxf(mx1, __shfl_xor_sync(0xffffffffu, mx1, 1));
        mx1 = fmaxf(mx1, __shfl_xor_sync(0xffffffffu, mx1, 2));

        float mn0 = fmaxf(m0, mx0), mn1 = fmaxf(m1, mx1);
        float sc0 = __expf(m0 - mn0), sc1 = __expf(m1 - mn1);
        m0 = mn0; m1 = mn1;

        float p[4][4];
        float rs0 = 0.f, rs1 = 0.f;
#pragma unroll
        for (int jf = 0; jf < 4; jf++) {
            p[jf][0] = __expf(sacc[jf][0] - m0);
            p[jf][1] = __expf(sacc[jf][1] - m0);
            p[jf][2] = __expf(sacc[jf][2] - m1);
            p[jf][3] = __expf(sacc[jf][3] - m1);
            rs0 += p[jf][0] + p[jf][1];
            rs1 += p[jf][2] + p[jf][3];
        }
        rs0 += __shfl_xor_sync(0xffffffffu, rs0, 1);
        rs0 += __shfl_xor_sync(0xffffffffu, rs0, 2);
        rs1 += __shfl_xor_sync(0xffffffffu, rs1, 1);
        rs1 += __shfl_xor_sync(0xffffffffu, rs1, 2);
        l0 = l0 * sc0 + rs0;
        l1 = l1 * sc1 + rs1;

#pragma unroll
        for (int nf = 0; nf < 16; nf++) {
            oacc[nf][0] *= sc0; oacc[nf][1] *= sc0;
            oacc[nf][2] *= sc1; oacc[nf][3] *= sc1;
        }

        // ---- O += P V (fp16, P register-resident A-frags) ----
#pragma unroll
        for (int kc = 0; kc < 2; kc++) {
            uint32_t pa[4];
            pa[0] = f16x2(p[2 * kc][0],     p[2 * kc][1]);
            pa[1] = f16x2(p[2 * kc][2],     p[2 * kc][3]);
            pa[2] = f16x2(p[2 * kc + 1][0], p[2 * kc + 1][1]);
            pa[3] = f16x2(p[2 * kc + 1][2], p[2 * kc + 1][3]);
#pragma unroll
            for (int nfp = 0; nfp < 8; nfp++) {
                uint4 vb = *(const uint4*)&Vf[((kc * 8 + nfp) * 32 + lane) * 4];
                mma_fp16(oacc[2 * nfp],     pa, vb.x, vb.y);
                mma_fp16(oacc[2 * nfp + 1], pa, vb.z, vb.w);
            }
        }

        __syncthreads();
        if (kt + 2 < NKT) issue(s, kt + 2);
        cp_commit();
    }

    // ---- normalize, stage O [128c][132], residual, write ----
    const int r0 = 16 * w + g2;
    float* OSf = (float*)smu;
    {
        float inv0 = 1.f / l0, inv1 = 1.f / l1;
#pragma unroll
        for (int nf = 0; nf < 16; nf++) {
            int c = 8 * nf + 2 * tid;
            OSf[c * 132 + r0]           = oacc[nf][0] * inv0;
            OSf[(c + 1) * 132 + r0]     = oacc[nf][1] * inv0;
            OSf[c * 132 + r0 + 8]       = oacc[nf][2] * inv1;
            OSf[(c + 1) * 132 + r0 + 8] = oacc[nf][3] * inv1;
        }
    }
    __syncthreads();

    const float gm = gamma[0];
    const float* xB  = x    + (size_t)b * C_ * N_ + N0;
    float*       saB = g_SA + (size_t)b * C_ * N_ + N0;
    for (int v = t; v < 4096; v += 256) {
        int c = v >> 5, q = (v & 31) * 4;
        float4 o  = *(float4*)&OSf[c * 132 + q];
        float4 xv = *(const float4*)(xB + (size_t)c * N_ + q);
        float4 rr = make_float4(gm * o.x + xv.x, gm * o.y + xv.y,
                                gm * o.z + xv.z, gm * o.w + xv.w);
        *(float4*)(saB + (size_t)c * N_ + q) = rr;
    }
}

// ---------------------------------------------------------------------------
extern "C" void kernel_launch(void* const* d_in, const int* in_sizes, int n_in,
                              void* d_out, int out_size)
{
    const float* x     = (const float*)d_in[0];
    const float* Wq    = (const float*)d_in[1];
    const float* bq    = (const float*)d_in[2];
    const float* Wk    = (const float*)d_in[3];
    const float* bk    = (const float*)d_in[4];
    const float* Wv    = (const float*)d_in[5];
    const float* bv    = (const float*)d_in[6];
    const float* gamma = (const float*)d_in[7];
    const float* Wo    = (const float*)d_in[8];
    const float* bo    = (const float*)d_in[9];
    float* out = (float*)d_out;

    float* SAp;
    cudaGetSymbolAddress((void**)&SAp, g_SA);

    cudaFuncSetAttribute(attn_kernel,
                         cudaFuncAttributeMaxDynamicSharedMemorySize, ATTN_SMEM_BYTES);

    dim3 pgrid(N_ / 64, B_);
    proj_pack_kernel<0><<<pgrid, 256>>>(x, Wq, bq);
    proj_pack_kernel<1><<<pgrid, 256>>>(x, Wk, bk);
    proj_pack_kernel<2><<<pgrid, 256>>>(x, Wv, bv);

    dim3 agrid(N_ / 128, B_);
    attn_kernel<<<agrid, 256, ATTN_SMEM_BYTES>>>(x, gamma);

    proj_kernel<<<pgrid, 256>>>(SAp, Wo, bo, out);
}